// round 1
// baseline (speedup 1.0000x reference)
#include <cuda_runtime.h>
#include <cstdint>

// DisparityWarping:
//   x:         [4,16,320,1024] f32
//   disparity: [4, 1,320,1024] f32 in [0,64)
// Output (concat, f32): warped [4,16,320,1024] then mask [4,1,320,1024] (0/1)
//
// warped[n,c,i,j] = bilinear sample of x[n,c] at (gy(i), gx(i,j)) with zeros
// padding; grid arithmetic replicated op-for-op against the JAX reference
// (IEEE div via __fdiv_rn, same associativity) so floor/boundary decisions
// match. gx_pix ~= j - d ; gy_pix ~= i (exact for i>=80, +-2^-25*159.5 else).
//
// mask[n,i,j] = (|gx_norm|<=1) && occlusion, where occlusion is the per-row
// scatter-max (last-write-wins == max) of j into trans[j]=max(j-int(d),0),
// gathered back, |back - j| <= 1.

#define H 320
#define W 1024
#define C 16
#define NB 4
#define HW (H * W)
#define CHW (C * HW)

__global__ __launch_bounds__(W, 2)
void disparity_warp_kernel(const float* __restrict__ x,
                           const float* __restrict__ disp,
                           float* __restrict__ out_img,
                           float* __restrict__ out_mask)
{
    const int row = blockIdx.x;          // n*H + i
    const int n = row / H;
    const int i = row - n * H;
    const int j = threadIdx.x;

    __shared__ int smax[W];
    smax[j] = 0;

    const float d = disp[(size_t)row * W + j];

    // ---- occlusion scatter (shared atomicMax == last-write-wins of ascending j)
    int trans = j - (int)d;              // int cast truncates; d >= 0 so == floor
    if (trans < 0) trans = 0;
    __syncthreads();                      // smax init complete
    atomicMax(&smax[trans], j);

    // ---- grid arithmetic, replicating reference fp32 op order exactly
    const float jm  = (float)j - d;                        // xs - disparity
    const float gxn = __fdiv_rn(2.0f * jm, 1023.0f) - 1.0f;
    const float gx  = ((gxn + 1.0f) * 1023.0f) * 0.5f;
    const float t   = __fdiv_rn(2.0f * (float)i, 319.0f);
    const float gyn = t - 1.0f;
    const float gy  = ((gyn + 1.0f) * 319.0f) * 0.5f;

    const float x0f = floorf(gx);
    const float y0f = floorf(gy);
    const float wx1 = gx - x0f;
    const float wx0 = 1.0f - wx1;
    const float wy1 = gy - y0f;
    const float wy0 = 1.0f - wy1;

    // per-corner validity (zeros padding), matching reference's float compares
    const float x1f = x0f + 1.0f;
    const float y1f = y0f + 1.0f;
    const float vx0 = (x0f >= 0.0f && x0f <= 1023.0f) ? 1.0f : 0.0f;
    const float vx1 = (x1f >= 0.0f && x1f <= 1023.0f) ? 1.0f : 0.0f;
    const float vy0 = (y0f >= 0.0f && y0f <= 319.0f)  ? 1.0f : 0.0f;
    const float vy1 = (y1f >= 0.0f && y1f <= 319.0f)  ? 1.0f : 0.0f;

    // clamped integer indices (safe addresses; invalid taps weighted to 0)
    int x0 = (int)x0f;     x0 = min(max(x0, 0), W - 1);
    int x1 = (int)x0f + 1; x1 = min(max(x1, 0), W - 1);
    int y0 = (int)y0f;     y0 = min(max(y0, 0), H - 1);
    int y1 = (int)y0f + 1; y1 = min(max(y1, 0), H - 1);

    const float w00 = (wx0 * wy0) * (vx0 * vy0);
    const float w01 = (wx1 * wy0) * (vx1 * vy0);
    const float w10 = (wx0 * wy1) * (vx0 * vy1);
    const float w11 = (wx1 * wy1) * (vx1 * vy1);

    const int o00 = y0 * W + x0;
    const int o01 = y0 * W + x1;
    const int o10 = y1 * W + x0;
    const int o11 = y1 * W + x1;

    const float* xb = x       + (size_t)n * CHW;
    float*       ob = out_img + (size_t)n * CHW + (size_t)i * W + j;

    // second-row contribution is exactly zero for most rows (wy1==0 for i>=80,
    // vy1==0 at the bottom edge); branch is uniform across the block since gy
    // depends only on i (w10/w11 share the wy1*vy1 factor except wx splits —
    // per-thread but overwhelmingly uniform).
    const bool need_row1 = (w10 != 0.0f) || (w11 != 0.0f);

    if (need_row1) {
        #pragma unroll
        for (int c = 0; c < C; ++c) {
            const float* p = xb + c * HW;
            float v = __ldg(p + o00) * w00 + __ldg(p + o01) * w01
                    + __ldg(p + o10) * w10 + __ldg(p + o11) * w11;
            ob[c * HW] = v;
        }
    } else {
        #pragma unroll
        for (int c = 0; c < C; ++c) {
            const float* p = xb + c * HW;
            ob[c * HW] = __ldg(p + o00) * w00 + __ldg(p + o01) * w01;
        }
    }

    // ---- occlusion gather + final mask
    __syncthreads();                      // all atomicMax done
    const int back = smax[trans];
    const int ad = back - j;
    const bool occ = (ad <= 1) && (ad >= -1);
    const bool inb = fabsf(gxn) <= 1.0f;  // |gy_norm|<=1 is always true
    out_mask[(size_t)row * W + j] = (occ && inb) ? 1.0f : 0.0f;
}

extern "C" void kernel_launch(void* const* d_in, const int* in_sizes, int n_in,
                              void* d_out, int out_size)
{
    const float* x    = (const float*)d_in[0];
    const float* disp = (const float*)d_in[1];
    float* out_img  = (float*)d_out;
    float* out_mask = (float*)d_out + (size_t)NB * CHW;

    dim3 grid(NB * H);
    dim3 block(W);
    disparity_warp_kernel<<<grid, block>>>(x, disp, out_img, out_mask);
}